// round 1
// baseline (speedup 1.0000x reference)
#include <cuda_runtime.h>
#include <math.h>

#define BATCH  8192
#define UNITS  1024
#define KTOT   2048          // IN_DIM + UNITS fused K
#define NCOL   4096          // 4*UNITS gate columns

// 128 MB scratch for z = [x|h] @ [W;U]  (device global: allocation-free rule)
__device__ float g_z[(size_t)BATCH * NCOL];

#define BM 128
#define BN 128
#define BK 16
#define TM 8
#define TN 8
// threads = (BM/TM)*(BN/TN) = 16*16 = 256

__global__ __launch_bounds__(256, 2)
void lstm_gemm_kernel(const float* __restrict__ x,
                      const float* __restrict__ h,
                      const float* __restrict__ W,
                      const float* __restrict__ U)
{
    __shared__ float As[BK][BM];   // transposed A tile
    __shared__ float Bs[BK][BN];

    const int bm = blockIdx.y * BM;
    const int bn = blockIdx.x * BN;
    const int tid = threadIdx.x;
    const int tx = tid % (BN / TN);   // 0..15
    const int ty = tid / (BN / TN);   // 0..15

    // A tile loads: 128x16 floats, 2 float4 per thread
    const int aRow  = tid / 4;          // 0..63 (two passes: +0, +64)
    const int aCol4 = (tid % 4) * 4;    // 0,4,8,12
    // B tile loads: 16x128 floats, 2 float4 per thread
    const int bRow  = tid / 32;         // 0..7 (two passes: +0, +8)
    const int bCol4 = (tid % 32) * 4;

    float acc[TM][TN];
    #pragma unroll
    for (int i = 0; i < TM; i++)
        #pragma unroll
        for (int j = 0; j < TN; j++) acc[i][j] = 0.0f;

    for (int k0 = 0; k0 < KTOT; k0 += BK) {
        // Select source halves (BK=16 divides 1024, so a tile never straddles)
        const float* __restrict__ Asrc = (k0 < 1024) ? x : h;
        const float* __restrict__ Bsrc = (k0 < 1024) ? W : U;
        const int kbase = (k0 < 1024) ? k0 : (k0 - 1024);

        // Load A tile (transposed into As)
        #pragma unroll
        for (int p = 0; p < 2; p++) {
            int r = aRow + p * 64;                    // row within tile
            const float4 v = *reinterpret_cast<const float4*>(
                &Asrc[(size_t)(bm + r) * 1024 + kbase + aCol4]);
            As[aCol4 + 0][r] = v.x;
            As[aCol4 + 1][r] = v.y;
            As[aCol4 + 2][r] = v.z;
            As[aCol4 + 3][r] = v.w;
        }
        // Load B tile (row-major)
        #pragma unroll
        for (int p = 0; p < 2; p++) {
            int r = bRow + p * 8;
            const float4 v = *reinterpret_cast<const float4*>(
                &Bsrc[(size_t)(kbase + r) * NCOL + bn + bCol4]);
            *reinterpret_cast<float4*>(&Bs[r][bCol4]) = v;
        }
        __syncthreads();

        #pragma unroll
        for (int kk = 0; kk < BK; kk++) {
            float regA[TM], regB[TN];
            #pragma unroll
            for (int i = 0; i < TM; i += 4) {
                float4 v = *reinterpret_cast<const float4*>(&As[kk][ty * TM + i]);
                regA[i + 0] = v.x; regA[i + 1] = v.y;
                regA[i + 2] = v.z; regA[i + 3] = v.w;
            }
            #pragma unroll
            for (int j = 0; j < TN; j += 4) {
                float4 v = *reinterpret_cast<const float4*>(&Bs[kk][tx * TN + j]);
                regB[j + 0] = v.x; regB[j + 1] = v.y;
                regB[j + 2] = v.z; regB[j + 3] = v.w;
            }
            #pragma unroll
            for (int i = 0; i < TM; i++)
                #pragma unroll
                for (int j = 0; j < TN; j++)
                    acc[i][j] = fmaf(regA[i], regB[j], acc[i][j]);
        }
        __syncthreads();
    }

    // Write z tile (vectorized)
    #pragma unroll
    for (int i = 0; i < TM; i++) {
        const size_t row = (size_t)(bm + ty * TM + i);
        #pragma unroll
        for (int j = 0; j < TN; j += 4) {
            float4 v = make_float4(acc[i][j], acc[i][j+1], acc[i][j+2], acc[i][j+3]);
            *reinterpret_cast<float4*>(&g_z[row * NCOL + bn + tx * TN + j]) = v;
        }
    }
}

__device__ __forceinline__ float sigmoidf_(float v) {
    return 1.0f / (1.0f + expf(-v));
}

__global__ __launch_bounds__(256)
void lstm_epilogue_kernel(const float* __restrict__ c_prev,
                          const float* __restrict__ bias,
                          const float* __restrict__ pf,
                          const float* __restrict__ pi,
                          const float* __restrict__ po,
                          float* __restrict__ out)
{
    const int idx = blockIdx.x * blockDim.x + threadIdx.x;  // 0 .. BATCH*UNITS-1
    const int u = idx & (UNITS - 1);
    const size_t zbase = (size_t)(idx >> 10) * NCOL;

    const float zf = g_z[zbase + u]        + bias[u];
    const float zi = g_z[zbase + u + 1024] + bias[u + 1024];
    const float zc = g_z[zbase + u + 2048] + bias[u + 2048];
    const float zo = g_z[zbase + u + 3072] + bias[u + 3072];

    const float cp = c_prev[idx];
    const float f  = sigmoidf_(zf + pf[u] * cp);
    const float ig = sigmoidf_(zi + pi[u] * cp);
    const float ct = tanhf(zc);
    const float c  = f * cp + ig * ct;
    const float o  = sigmoidf_(zo + po[u] * c);
    const float hv = o * tanhf(c);

    out[idx] = hv;                                  // h first
    out[(size_t)BATCH * UNITS + idx] = c;           // then c
}

extern "C" void kernel_launch(void* const* d_in, const int* in_sizes, int n_in,
                              void* d_out, int out_size)
{
    const float* x      = (const float*)d_in[0];  // inputs           [8192,1024]
    const float* c_prev = (const float*)d_in[1];  // c_prev           [8192,1024]
    const float* h_prev = (const float*)d_in[2];  // h_prev           [8192,1024]
    const float* W      = (const float*)d_in[3];  // kernel           [1024,4096]
    const float* U      = (const float*)d_in[4];  // recurrent_kernel [1024,4096]
    const float* bias   = (const float*)d_in[5];  // bias             [4096]
    const float* pf     = (const float*)d_in[6];  // peephole_f       [1024]
    const float* pi     = (const float*)d_in[7];  // peephole_i       [1024]
    const float* po     = (const float*)d_in[8];  // peephole_o       [1024]
    float* out = (float*)d_out;

    dim3 ggrid(NCOL / BN, BATCH / BM);   // (32, 64)
    lstm_gemm_kernel<<<ggrid, 256>>>(x, h_prev, W, U);

    const int total = BATCH * UNITS;
    lstm_epilogue_kernel<<<total / 256, 256>>>(c_prev, bias, pf, pi, po, out);
}

// round 3
// speedup vs baseline: 2.6934x; 2.6934x over previous
#include <cuda_runtime.h>
#include <cuda_bf16.h>
#include <cstdint>
#include <math.h>

#define BATCH 8192
#define UNITS 1024
#define KTOT  2048
#define NCOL  4096

// ---------------- device scratch (allocation-free rule) ----------------
__device__ __nv_bfloat16 gA_hi[(size_t)BATCH * KTOT];
__device__ __nv_bfloat16 gA_lo[(size_t)BATCH * KTOT];
__device__ __nv_bfloat16 gB_hi[(size_t)NCOL * KTOT];   // [n][k] K-major (transposed)
__device__ __nv_bfloat16 gB_lo[(size_t)NCOL * KTOT];

// ---------------- helpers ----------------
__device__ __forceinline__ uint32_t smem_to_u32(const void* p) {
    uint32_t a;
    asm("{ .reg .u64 t; cvta.to.shared.u64 t, %1; cvt.u32.u64 %0, t; }" : "=r"(a) : "l"(p));
    return a;
}
__device__ __forceinline__ void cp16(uint32_t dst, const void* src) {
    asm volatile("cp.async.cg.shared.global [%0], [%1], 16;" :: "r"(dst), "l"(src));
}
#define CP_COMMIT() asm volatile("cp.async.commit_group;" ::: "memory")

#define LDSM4(r, addr) \
    asm volatile("ldmatrix.sync.aligned.m8n8.x4.shared.b16 {%0,%1,%2,%3}, [%4];" \
        : "=r"((r)[0]), "=r"((r)[1]), "=r"((r)[2]), "=r"((r)[3]) : "r"(addr))

__device__ __forceinline__ void mma_bf16(float* c, const uint32_t* a, uint32_t b0, uint32_t b1) {
    asm volatile("mma.sync.aligned.m16n8k16.row.col.f32.bf16.bf16.f32 "
        "{%0,%1,%2,%3}, {%4,%5,%6,%7}, {%8,%9}, {%0,%1,%2,%3};"
        : "+f"(c[0]), "+f"(c[1]), "+f"(c[2]), "+f"(c[3])
        : "r"(a[0]), "r"(a[1]), "r"(a[2]), "r"(a[3]), "r"(b0), "r"(b1));
}

__device__ __forceinline__ float sigf(float v) { return 1.0f / (1.0f + expf(-v)); }

// ---------------- conversion kernels ----------------
__global__ __launch_bounds__(256)
void convA_kernel(const float4* __restrict__ x4, const float4* __restrict__ h4)
{
    size_t idx4 = (size_t)blockIdx.x * 256 + threadIdx.x;   // 0 .. 8192*512-1
    int m  = (int)(idx4 >> 9);
    int c4 = (int)(idx4 & 511);
    float4 v = (c4 < 256) ? x4[(size_t)m * 256 + c4]
                          : h4[(size_t)m * 256 + (c4 - 256)];
    __nv_bfloat16 hx = __float2bfloat16_rn(v.x);
    __nv_bfloat16 hy = __float2bfloat16_rn(v.y);
    __nv_bfloat16 hz = __float2bfloat16_rn(v.z);
    __nv_bfloat16 hw = __float2bfloat16_rn(v.w);
    __nv_bfloat162 ph0; ph0.x = hx; ph0.y = hy;
    __nv_bfloat162 ph1; ph1.x = hz; ph1.y = hw;
    ((__nv_bfloat162*)gA_hi)[idx4 * 2]     = ph0;
    ((__nv_bfloat162*)gA_hi)[idx4 * 2 + 1] = ph1;
    __nv_bfloat162 pl0, pl1;
    pl0.x = __float2bfloat16_rn(v.x - __bfloat162float(hx));
    pl0.y = __float2bfloat16_rn(v.y - __bfloat162float(hy));
    pl1.x = __float2bfloat16_rn(v.z - __bfloat162float(hz));
    pl1.y = __float2bfloat16_rn(v.w - __bfloat162float(hw));
    ((__nv_bfloat162*)gA_lo)[idx4 * 2]     = pl0;
    ((__nv_bfloat162*)gA_lo)[idx4 * 2 + 1] = pl1;
}

__global__ __launch_bounds__(256)
void convB_kernel(const float* __restrict__ W, const float* __restrict__ U)
{
    __shared__ float tile[32][33];
    const int n0 = blockIdx.x * 32, k0 = blockIdx.y * 32;
    #pragma unroll
    for (int i = 0; i < 4; i++) {
        int k = k0 + threadIdx.y + i * 8;
        int n = n0 + threadIdx.x;
        float v = (k < 1024) ? W[(size_t)k * 4096 + n] : U[(size_t)(k - 1024) * 4096 + n];
        tile[threadIdx.y + i * 8][threadIdx.x] = v;
    }
    __syncthreads();
    #pragma unroll
    for (int i = 0; i < 4; i++) {
        int nn = threadIdx.y + i * 8;   // n within tile
        int kk = threadIdx.x;           // k within tile
        float v = tile[kk][nn];
        __nv_bfloat16 hi = __float2bfloat16_rn(v);
        __nv_bfloat16 lo = __float2bfloat16_rn(v - __bfloat162float(hi));
        gB_hi[(size_t)(n0 + nn) * KTOT + k0 + kk] = hi;
        gB_lo[(size_t)(n0 + nn) * KTOT + k0 + kk] = lo;
    }
}

// ---------------- fused MMA + LSTM-gate kernel ----------------
// CTA tile: 128 (M) x 128 (N) x BK=32. N cols interleaved: col = 4*u_local + gate.
// SMEM per stage: 4 tiles (Ahi, Alo, Bhi, Blo), each 128 rows x 80B (padded) = 40960B.
#define PADB 80
#define TILE_B (128 * PADB)          // 10240
#define OFF_AHI 0
#define OFF_ALO TILE_B
#define OFF_BHI (2 * TILE_B)
#define OFF_BLO (3 * TILE_B)
#define STAGE_B (4 * TILE_B)         // 40960
#define SMEM_TOTAL (2 * STAGE_B)     // 81920
#define NITER 64                     // 2048 / 32
#define ZSTRIDE 130                  // epilogue z smem stride (floats)

__global__ __launch_bounds__(256, 2)
void lstm_mma_kernel(const float* __restrict__ c_prev,
                     const float* __restrict__ bias,
                     const float* __restrict__ pf,
                     const float* __restrict__ pi,
                     const float* __restrict__ po,
                     float* __restrict__ out)
{
    extern __shared__ char smc[];
    const uint32_t sb = smem_to_u32(smc);
    const int tid  = threadIdx.x;
    const int lane = tid & 31;
    const int warp = tid >> 5;
    const int warp_m = warp & 3;        // 4 warps over M (32 rows each)
    const int warp_n = warp >> 2;       // 2 warps over N (64 cols each)
    const int bm = blockIdx.y * 128;
    const int u0 = blockIdx.x * 32;     // 32 units per CTA

    // ---- per-thread load slots: 2 per tile (A: r=tid>>2 (+64), c=tid&3) ----
    const int r0 = tid >> 2, cch = tid & 3;
    uint32_t soff[2], aoff[2], boff[2];
    #pragma unroll
    for (int s = 0; s < 2; s++) {
        const int r = r0 + s * 64;
        soff[s] = (uint32_t)(r * PADB + cch * 16);
        aoff[s] = (uint32_t)(((size_t)(bm + r) * KTOT + cch * 8) * 2);
        const int ng = (r & 3) * 1024 + u0 + (r >> 2);   // gate-interleaved B row
        boff[s] = (uint32_t)(((size_t)ng * KTOT + cch * 8) * 2);
    }
    const char* pAh = (const char*)gA_hi;
    const char* pAl = (const char*)gA_lo;
    const char* pBh = (const char*)gB_hi;
    const char* pBl = (const char*)gB_lo;

    // prologue: load stages 0 and 1 (k-offset advances 64 bytes per iter)
    #pragma unroll
    for (int i = 0; i < 2; i++) {
        const uint32_t st = sb + i * STAGE_B;
        const uint32_t kb = (uint32_t)(i * 64);
        #pragma unroll
        for (int s = 0; s < 2; s++) {
            cp16(st + OFF_AHI + soff[s], pAh + aoff[s] + kb);
            cp16(st + OFF_ALO + soff[s], pAl + aoff[s] + kb);
            cp16(st + OFF_BHI + soff[s], pBh + boff[s] + kb);
            cp16(st + OFF_BLO + soff[s], pBl + boff[s] + kb);
        }
        CP_COMMIT();
    }

    float acc[2][8][4];
    #pragma unroll
    for (int mt = 0; mt < 2; mt++)
        #pragma unroll
        for (int nt = 0; nt < 8; nt++)
            #pragma unroll
            for (int q = 0; q < 4; q++) acc[mt][nt][q] = 0.0f;

    // ldmatrix address components (fixed per thread)
    const int a_row = warp_m * 32 + (lane & 15);        // + mt*16
    const int a_kc  = (lane >> 4);                      // + ks*2
    const int b_row = warp_n * 64 + (lane & 7) + ((lane >> 4) & 1) * 8;  // + nt2*16
    const int b_kc  = ((lane >> 3) & 1);                // + ks*2

    for (int i = 0; i < NITER; i++) {
        if (i < NITER - 1) asm volatile("cp.async.wait_group 1;" ::: "memory");
        else               asm volatile("cp.async.wait_group 0;" ::: "memory");
        __syncthreads();

        const uint32_t st = sb + (i & 1) * STAGE_B;
        #pragma unroll
        for (int ks = 0; ks < 2; ks++) {
            uint32_t ah[2][4], al[2][4], bh[4][4], bl[4][4];
            #pragma unroll
            for (int mt = 0; mt < 2; mt++)
                LDSM4(ah[mt], st + OFF_AHI + (uint32_t)((a_row + mt * 16) * PADB + (a_kc + ks * 2) * 16));
            #pragma unroll
            for (int nt2 = 0; nt2 < 4; nt2++)
                LDSM4(bh[nt2], st + OFF_BHI + (uint32_t)((b_row + nt2 * 16) * PADB + (b_kc + ks * 2) * 16));
            // hi x hi
            #pragma unroll
            for (int mt = 0; mt < 2; mt++)
                #pragma unroll
                for (int nt = 0; nt < 8; nt++)
                    mma_bf16(acc[mt][nt], ah[mt], bh[nt >> 1][(nt & 1) * 2], bh[nt >> 1][(nt & 1) * 2 + 1]);
            // lo x hi
            #pragma unroll
            for (int mt = 0; mt < 2; mt++)
                LDSM4(al[mt], st + OFF_ALO + (uint32_t)((a_row + mt * 16) * PADB + (a_kc + ks * 2) * 16));
            #pragma unroll
            for (int mt = 0; mt < 2; mt++)
                #pragma unroll
                for (int nt = 0; nt < 8; nt++)
                    mma_bf16(acc[mt][nt], al[mt], bh[nt >> 1][(nt & 1) * 2], bh[nt >> 1][(nt & 1) * 2 + 1]);
            // hi x lo
            #pragma unroll
            for (int nt2 = 0; nt2 < 4; nt2++)
                LDSM4(bl[nt2], st + OFF_BLO + (uint32_t)((b_row + nt2 * 16) * PADB + (b_kc + ks * 2) * 16));
            #pragma unroll
            for (int mt = 0; mt < 2; mt++)
                #pragma unroll
                for (int nt = 0; nt < 8; nt++)
                    mma_bf16(acc[mt][nt], ah[mt], bl[nt >> 1][(nt & 1) * 2], bl[nt >> 1][(nt & 1) * 2 + 1]);
        }
        __syncthreads();

        if (i + 2 < NITER) {
            const uint32_t stn = sb + (i & 1) * STAGE_B;
            const uint32_t kb  = (uint32_t)((i + 2) * 64);
            #pragma unroll
            for (int s = 0; s < 2; s++) {
                cp16(stn + OFF_AHI + soff[s], pAh + aoff[s] + kb);
                cp16(stn + OFF_ALO + soff[s], pAl + aoff[s] + kb);
                cp16(stn + OFF_BHI + soff[s], pBh + boff[s] + kb);
                cp16(stn + OFF_BLO + soff[s], pBl + boff[s] + kb);
            }
            CP_COMMIT();
        }
    }

    // ---- epilogue: stage z tile to smem, then fused LSTM gates ----
    float* z = (float*)smc;   // 128 x ZSTRIDE floats = 66560 B (fits in 81920)
    #pragma unroll
    for (int mt = 0; mt < 2; mt++) {
        const int row = warp_m * 32 + mt * 16 + (lane >> 2);
        #pragma unroll
        for (int nt = 0; nt < 8; nt++) {
            const int col = warp_n * 64 + nt * 8 + (lane & 3) * 2;
            z[row * ZSTRIDE + col]           = acc[mt][nt][0];
            z[row * ZSTRIDE + col + 1]       = acc[mt][nt][1];
            z[(row + 8) * ZSTRIDE + col]     = acc[mt][nt][2];
            z[(row + 8) * ZSTRIDE + col + 1] = acc[mt][nt][3];
        }
    }
    __syncthreads();

    #pragma unroll
    for (int t = tid; t < 128 * 32; t += 256) {
        const int m = t >> 5;          // 0..127
        const int u = t & 31;          // 0..31
        const int mg = bm + m;
        const int ug = u0 + u;
        const float zf = z[m * ZSTRIDE + 4 * u]     + bias[ug];
        const float zi = z[m * ZSTRIDE + 4 * u + 1] + bias[1024 + ug];
        const float zc = z[m * ZSTRIDE + 4 * u + 2] + bias[2048 + ug];
        const float zo = z[m * ZSTRIDE + 4 * u + 3] + bias[3072 + ug];
        const float cp = c_prev[(size_t)mg * UNITS + ug];
        const float f  = sigf(zf + pf[ug] * cp);
        const float ig = sigf(zi + pi[ug] * cp);
        const float ct = tanhf(zc);
        const float c  = f * cp + ig * ct;
        const float o  = sigf(zo + po[ug] * c);
        out[(size_t)mg * UNITS + ug] = o * tanhf(c);
        out[(size_t)BATCH * UNITS + (size_t)mg * UNITS + ug] = c;
    }
}

// ---------------- launch ----------------
extern "C" void kernel_launch(void* const* d_in, const int* in_sizes, int n_in,
                              void* d_out, int out_size)
{
    const float* x      = (const float*)d_in[0];
    const float* c_prev = (const float*)d_in[1];
    const float* h_prev = (const float*)d_in[2];
    const float* W      = (const float*)d_in[3];
    const float* U      = (const float*)d_in[4];
    const float* bias   = (const float*)d_in[5];
    const float* pf     = (const float*)d_in[6];
    const float* pi     = (const float*)d_in[7];
    const float* po     = (const float*)d_in[8];
    float* out = (float*)d_out;

    convA_kernel<<<(BATCH * KTOT / 4) / 256, 256>>>((const float4*)x, (const float4*)h_prev);
    convB_kernel<<<dim3(NCOL / 32, KTOT / 32), dim3(32, 8)>>>(W, U);

    cudaFuncSetAttribute(lstm_mma_kernel,
                         cudaFuncAttributeMaxDynamicSharedMemorySize, SMEM_TOTAL);
    lstm_mma_kernel<<<dim3(UNITS / 32, BATCH / 128), 256, SMEM_TOTAL>>>(
        c_prev, bias, pf, pi, po, out);
}